// round 14
// baseline (speedup 1.0000x reference)
#include <cuda_runtime.h>
#include <cuda_fp16.h>
#include <cstdint>

#define NN 20000
#define MM 64
#define WL 8
#define NPAIRS (MM*NN*WL)      /* 10,240,000 pairs per X tensor */
#define NPB 16                 /* n's per chunk */
#define NCHUNK (NN/NPB)        /* 1250 */
#define NBLK 148               /* one block per SM */
#define NT 1024                /* 16 producer + 16 consumer warps */
#define NPROD 512
#define NCONS 512
#define NSTG 4

/* ---- stage: F1h [64][17] uint2 (8704 B) + F2f [16][67] float4 (17152 B) ---- */
#define STG_F2    8704
#define STG_BYTES 25856

/* ---- shared memory layout (bytes) ---- */
#define OFF_STG   (NN*4)                      /* 80000 : u8 table (4 batches/word) */
#define OFF_PIA   (OFF_STG + NSTG*STG_BYTES)  /* 183424: piA ull[32*64] dup f32x2  */
#define OFF_PIB   (OFF_PIA + 16384)           /* 199808: piB ull[32*64]            */
#define OFF_P12   (OFF_PIB + 16384)           /* 216192: pi1, pi2                  */
#define OFF_RED   (OFF_P12 + 512)             /* 216704: float4[4][16][2]          */
#define OFF_CTL   (OFF_RED + 2048)            /* 218752: hdr[4] + 8 mbarriers      */
#define SMEM_TOTAL (OFF_CTL + 128)            /* 218880 */

#define FS (1.0f/(255.0f*255.0f))

typedef unsigned long long ull;

// ---------------- device scratch (static) ------------------------------------
__device__ unsigned g_cx1[NPAIRS];   // packed (i0 | i1<<16)
__device__ unsigned g_cx2[NPAIRS];
__device__ unsigned g_tabB8[NN];     // a1 as 4 x u8 (gather table for iter 1)
__device__ float4   g_tabA32[NN];    // a1 exact f32 (finalize sidecar)
__device__ ull      g_piA[2048];     // dup f32x2 pi (even k), from iter-0 block 0
__device__ ull      g_piB[2048];     // dup f32x2 pi (odd k)
__device__ float    g_p12[2*MM];     // pi1, pi2
__device__ int      g_tick[2] = {0, 0};

// ---------------- small helpers ----------------------------------------------
__device__ __forceinline__ unsigned s2u(const void* p) {
    return (unsigned)__cvta_generic_to_shared(p);
}
__device__ __forceinline__ void mbar_init(unsigned a, unsigned cnt) {
    asm volatile("mbarrier.init.shared.b64 [%0], %1;" :: "r"(a), "r"(cnt) : "memory");
}
__device__ __forceinline__ void mbar_arrive(unsigned a) {
    asm volatile("mbarrier.arrive.release.cta.shared::cta.b64 _, [%0];" :: "r"(a) : "memory");
}
__device__ __forceinline__ void mbar_wait(unsigned a, unsigned parity) {
    asm volatile(
        "{\n\t.reg .pred P;\n\t"
        "WL_%=:\n\t"
        "mbarrier.try_wait.parity.acquire.cta.shared::cta.b64 P, [%0], %1, 0x989680;\n\t"
        "@P bra.uni WD_%=;\n\t"
        "bra.uni WL_%=;\n\t"
        "WD_%=:\n\t}"
        :: "r"(a), "r"(parity) : "memory");
}
__device__ __forceinline__ ull pack2(float lo, float hi) {
    ull r; asm("mov.b64 %0, {%1, %2};" : "=l"(r) : "f"(lo), "f"(hi)); return r;
}
__device__ __forceinline__ float2 unpack2(ull v) {
    float2 f; asm("mov.b64 {%0, %1}, %2;" : "=f"(f.x), "=f"(f.y) : "l"(v)); return f;
}
__device__ __forceinline__ void fma2(ull& d, ull a, ull b) {
    asm("fma.rn.f32x2 %0, %1, %2, %0;" : "+l"(d) : "l"(a), "l"(b));
}
// u8x4 word -> exact half2 of bytes {b0,b1} / {b2,b3} (PRMT exponent-offset trick)
__device__ __forceinline__ __half2 h1024() {
    unsigned u = 0x64006400u; return *(__half2*)&u;
}
__device__ __forceinline__ __half2 cvtlo(unsigned A) {
    unsigned r = __byte_perm(A, 0x64646464u, 0x4140);
    return __hsub2(*(__half2*)&r, h1024());
}
__device__ __forceinline__ __half2 cvthi(unsigned A) {
    unsigned r = __byte_perm(A, 0x64646464u, 0x4342);
    return __hsub2(*(__half2*)&r, h1024());
}
// gather: 8 independent products, max tree (raw byte products, >= 0)
__device__ __forceinline__ void gath8(const unsigned* pk, const unsigned* __restrict__ tab,
                                      __half2& ga, __half2& gb) {
    __half2 px[8], py[8];
    #pragma unroll
    for (int w = 0; w < 8; w++) {
        unsigned A = tab[pk[w] & 0xFFFFu];
        unsigned B = tab[pk[w] >> 16];
        px[w] = __hmul2(cvtlo(A), cvtlo(B));
        py[w] = __hmul2(cvthi(A), cvthi(B));
    }
    #pragma unroll
    for (int s = 4; s > 0; s >>= 1)
        #pragma unroll
        for (int w = 0; w < s; w++) {
            px[w] = __hmax2(px[w], px[w + s]);
            py[w] = __hmax2(py[w], py[w + s]);
        }
    ga = px[0]; gb = py[0];
}
__device__ __forceinline__ unsigned q8x4(float a, float b, float c, float d) {
    unsigned r =  __float2uint_rn(__saturatef(a) * 255.f);
    r |= __float2uint_rn(__saturatef(b) * 255.f) << 8;
    r |= __float2uint_rn(__saturatef(c) * 255.f) << 16;
    r |= __float2uint_rn(__saturatef(d) * 255.f) << 24;
    return r;
}

// ---------------- main iteration kernel --------------------------------------
template<int ITER>
__global__ void __launch_bounds__(NT, 1) k_iter(const float* __restrict__ a0,
                                                const float* __restrict__ Wm,
                                                const void* __restrict__ x1,
                                                const void* __restrict__ x2,
                                                float* __restrict__ out) {
    extern __shared__ char smem[];
    unsigned* tabu = (unsigned*)smem;                 // [NN] u8x4
    ull*      piAq = (ull*)   (smem + OFF_PIA);       // [32*64] dup f32x2 (even k)
    ull*      piBq = (ull*)   (smem + OFF_PIB);       // [32*64] dup f32x2 (odd k)
    float*    pi1s = (float*) (smem + OFF_P12);
    float*    pi2s = pi1s + MM;
    float4*   red4 = (float4*)(smem + OFF_RED);       // [4][16][2]
    float*    redf = (float*) (smem + OFF_RED);
    volatile int* hdr = (volatile int*)(smem + OFF_CTL);  // [4]
    const unsigned mb_full  = s2u(smem + OFF_CTL + 16);   // 4 x 8B
    const unsigned mb_empty = s2u(smem + OFF_CTL + 48);   // 4 x 8B

    const int tid  = threadIdx.x;
    const int warp = tid >> 5, lane = tid & 31;

    // reset the OTHER iter's ticket for the next launch/replay (R12-proven)
    if (blockIdx.x == 0 && tid == 0) g_tick[ITER ^ 1] = 0;
    if (tid < NSTG) {
        mbar_init(mb_full  + 8*tid, NPROD);
        mbar_init(mb_empty + 8*tid, NCONS);
    }

    int is64 = 0;

    if (ITER == 0) {
        // ===== preamble: u8 4-batch a-table from a0 =====
        for (int i = tid; i < NN; i += NT)
            tabu[i] = q8x4(__ldg(a0 + i), __ldg(a0 + NN + i),
                           __ldg(a0 + 2*NN + i), __ldg(a0 + 3*NN + i));

        // ===== preamble: softmax over 64x64 W -> piA/piB (dup f32x2), pi1, pi2 =====
        {
            float* sp = (float*)(smem + OFF_STG);
            float v4[4];
            float lm = -1e30f;
            #pragma unroll
            for (int t = 0; t < 4; t++) {
                float v = __ldg(Wm + tid + t*NT);
                v4[t] = v;
                lm = fmaxf(lm, v);
            }
            #pragma unroll
            for (int off = 16; off > 0; off >>= 1)
                lm = fmaxf(lm, __shfl_xor_sync(0xFFFFFFFFu, lm, off));
            if (lane == 0) redf[warp] = lm;
            __syncthreads();
            float m = -1e30f;
            #pragma unroll
            for (int w = 0; w < 32; w++) m = fmaxf(m, redf[w]);
            __syncthreads();
            float ls = 0.f;
            #pragma unroll
            for (int t = 0; t < 4; t++) {
                float e = expf(v4[t] - m);
                sp[tid + t*NT] = e;
                ls += e;
            }
            #pragma unroll
            for (int off = 16; off > 0; off >>= 1)
                ls += __shfl_xor_sync(0xFFFFFFFFu, ls, off);
            if (lane == 0) redf[32 + warp] = ls;
            __syncthreads();
            float tot = 0.f;
            #pragma unroll
            for (int w = 0; w < 32; w++) tot += redf[32 + w];
            const float inv = 1.f / tot;

            for (int i = tid; i < 2048; i += NT) {
                int kp = i >> 6, j = i & 63;
                float p0 = sp[j*MM + 2*kp] * inv;
                float p1 = sp[j*MM + 2*kp + 1] * inv;
                ull q0 = pack2(p0, p0), q1 = pack2(p1, p1);
                piAq[i] = q0; piBq[i] = q1;
                if (blockIdx.x == 0) { g_piA[i] = q0; g_piB[i] = q1; }  // for iter 1
            }
            if (tid < MM) {
                float s = 0.f;
                #pragma unroll 16
                for (int k = 0; k < MM; k++) s += sp[tid*MM + k];
                pi1s[tid] = s * inv;
                if (blockIdx.x == 0) g_p12[tid] = s * inv;
            } else if (tid < 2*MM) {
                int k = tid - MM;
                float s = 0.f;
                #pragma unroll 16
                for (int j = 0; j < MM; j++) s += sp[j*MM + k];
                pi2s[k] = s * inv;
                if (blockIdx.x == 0) g_p12[tid] = s * inv;
            }
        }

        // ===== preamble: dtype probe =====
        {
            const unsigned* x1u = (const unsigned*)x1;
            int nz = (x1u[2*tid + 1] != 0u) | (x1u[2*(tid + NT) + 1] != 0u);
            is64 = !__syncthreads_or(nz);
        }
    } else {
        // ===== preamble: table from a1 (u8), pi from globals (iter-0 ordering) ====
        for (int i = tid; i < NN; i += NT) tabu[i] = g_tabB8[i];
        for (int i = tid; i < 2048; i += NT) { piAq[i] = g_piA[i]; piBq[i] = g_piB[i]; }
        if (tid < 2*MM) pi1s[tid] = g_p12[tid];   // pi2s = pi1s + 64
    }
    __syncthreads();   // scratch dead; tab/pi/mbar visible

    if (tid < NPROD) {
        // ============ PRODUCER: 2 (j, nl) tasks per thread per chunk ============
        for (int i = 0; ; i++) {
            const int s = i & 3, ks = i >> 2;
            if (i >= NSTG) mbar_wait(mb_empty + 8*s, (ks - 1) & 1);
            if (tid == 0) hdr[s] = atomicAdd(&g_tick[ITER], 1);
            asm volatile("bar.sync 1, %0;" :: "n"(NPROD) : "memory");
            const int chunk = hdr[s];
            if (chunk >= NCHUNK) { mbar_arrive(mb_full + 8*s); break; }
            const int n0 = chunk * NPB;
            uint2*  F1h = (uint2*) (smem + OFF_STG + s*STG_BYTES);
            float4* F2f = (float4*)(smem + OFF_STG + s*STG_BYTES + STG_F2);

            #pragma unroll
            for (int p = 0; p < 2; p++) {
                const int t  = p*NPROD + tid;
                const int j  = t >> 4;
                const int nl = t & 15;
                const size_t pb = ((size_t)j * NN + n0 + nl) * WL;
                unsigned pk1[8], pk2[8];
                if (ITER == 0) {
                    if (is64) {
                        const uint4* c1 = (const uint4*)x1 + pb;
                        const uint4* c2 = (const uint4*)x2 + pb;
                        #pragma unroll
                        for (int w = 0; w < 8; w++) { uint4 v = __ldcs(c1 + w); pk1[w] = v.x | (v.z << 16); }
                        #pragma unroll
                        for (int w = 0; w < 8; w++) { uint4 v = __ldcs(c2 + w); pk2[w] = v.x | (v.z << 16); }
                    } else {
                        const uint4* c1 = (const uint4*)x1 + (pb >> 1);
                        const uint4* c2 = (const uint4*)x2 + (pb >> 1);
                        #pragma unroll
                        for (int w = 0; w < 4; w++) {
                            uint4 v = __ldcs(c1 + w);
                            pk1[2*w] = v.x | (v.y << 16); pk1[2*w+1] = v.z | (v.w << 16);
                        }
                        #pragma unroll
                        for (int w = 0; w < 4; w++) {
                            uint4 v = __ldcs(c2 + w);
                            pk2[2*w] = v.x | (v.y << 16); pk2[2*w+1] = v.z | (v.w << 16);
                        }
                    }
                    ((uint4*)(g_cx1 + pb))[0] = make_uint4(pk1[0], pk1[1], pk1[2], pk1[3]);
                    ((uint4*)(g_cx1 + pb))[1] = make_uint4(pk1[4], pk1[5], pk1[6], pk1[7]);
                    ((uint4*)(g_cx2 + pb))[0] = make_uint4(pk2[0], pk2[1], pk2[2], pk2[3]);
                    ((uint4*)(g_cx2 + pb))[1] = make_uint4(pk2[4], pk2[5], pk2[6], pk2[7]);
                } else {
                    const uint4* c1 = (const uint4*)(g_cx1 + pb);
                    const uint4* c2 = (const uint4*)(g_cx2 + pb);
                    uint4 q0 = __ldg(c1), q1 = __ldg(c1 + 1);
                    uint4 r0 = __ldg(c2), r1 = __ldg(c2 + 1);
                    pk1[0]=q0.x; pk1[1]=q0.y; pk1[2]=q0.z; pk1[3]=q0.w;
                    pk1[4]=q1.x; pk1[5]=q1.y; pk1[6]=q1.z; pk1[7]=q1.w;
                    pk2[0]=r0.x; pk2[1]=r0.y; pk2[2]=r0.z; pk2[3]=r0.w;
                    pk2[4]=r1.x; pk2[5]=r1.y; pk2[6]=r1.z; pk2[7]=r1.w;
                }
                __half2 f1a, f1b, f2a, f2b;
                gath8(pk1, tabu, f1a, f1b);
                gath8(pk2, tabu, f2a, f2b);
                F1h[j*17 + nl] = make_uint2(*(unsigned*)&f1a, *(unsigned*)&f1b);  // raw products
                float2 lo = __half22float2(f2a), hi = __half22float2(f2b);
                F2f[nl*67 + j] = make_float4(lo.x*FS, lo.y*FS, hi.x*FS, hi.y*FS); // true units
            }
            mbar_arrive(mb_full + 8*s);
        }
    } else {
        // ============ CONSUMER: bilinear + reduce + finalize =====================
        const int ctid = tid - NPROD;          // 0..511
        const int jj = ctid & 63;              // pi column
        const int g8 = ctid >> 6;              // 0..7 -> n = g8, g8+8
        const int half = (ctid >> 5) & 1;
        const float p1 = pi1s[jj], p2 = pi2s[jj];
        for (int i = 0; ; i++) {
            const int s = i & 3, ks = i >> 2;
            mbar_wait(mb_full + 8*s, ks & 1);
            const int chunk = hdr[s];
            if (chunk >= NCHUNK) break;
            const int n0 = chunk * NPB;
            const uint2*  F1h = (const uint2*) (smem + OFF_STG + s*STG_BYTES);
            const float4* F2f = (const float4*)(smem + OFF_STG + s*STG_BYTES + STG_F2);

            ull mv00 = 0ull, mv01 = 0ull, mv10 = 0ull, mv11 = 0ull;   // [n][b01/b23]
            const ulonglong2* fbA = (const ulonglong2*)(F2f + g8*67);
            const ulonglong2* fbB = (const ulonglong2*)(F2f + (g8+8)*67);
            #pragma unroll 8
            for (int kp = 0; kp < 32; kp++) {
                ull pwx = piAq[kp*64 + jj];
                ull pwy = piBq[kp*64 + jj];
                ulonglong2 A0 = fbA[2*kp], B0 = fbA[2*kp + 1];
                ulonglong2 A1 = fbB[2*kp], B1 = fbB[2*kp + 1];
                fma2(mv00, pwx, A0.x); fma2(mv01, pwx, A0.y);
                fma2(mv00, pwy, B0.x); fma2(mv01, pwy, B0.y);
                fma2(mv10, pwx, A1.x); fma2(mv11, pwx, A1.y);
                fma2(mv10, pwy, B1.x); fma2(mv11, pwy, B1.y);
            }
            uint2  hpA  = F1h[jj*17 + g8];
            uint2  hpB  = F1h[jj*17 + g8 + 8];
            float4 f2vA = F2f[g8*67 + jj];
            float4 f2vB = F2f[(g8+8)*67 + jj];
            mbar_arrive(mb_empty + 8*s);   // stage reads done -> release early

            #pragma unroll
            for (int r = 0; r < 2; r++) {
                const int n = g8 + r*8;
                float2 ma = unpack2(r ? mv10 : mv00);
                float2 mb = unpack2(r ? mv11 : mv01);
                uint2  hp  = r ? hpB : hpA;
                float4 f2v = r ? f2vB : f2vA;
                float2 f01 = __half22float2(*(__half2*)&hp.x);
                float2 f23 = __half22float2(*(__half2*)&hp.y);
                float4 c;   // c = FS*f1raw*(p1 - mv) + p2*F2true
                c.x = FS*f01.x*(p1 - ma.x) + p2*f2v.x;
                c.y = FS*f01.y*(p1 - ma.y) + p2*f2v.y;
                c.z = FS*f23.x*(p1 - mb.x) + p2*f2v.z;
                c.w = FS*f23.y*(p1 - mb.y) + p2*f2v.w;
                #pragma unroll
                for (int off = 16; off > 0; off >>= 1) {
                    c.x += __shfl_xor_sync(0xFFFFFFFFu, c.x, off);
                    c.y += __shfl_xor_sync(0xFFFFFFFFu, c.y, off);
                    c.z += __shfl_xor_sync(0xFFFFFFFFu, c.z, off);
                    c.w += __shfl_xor_sync(0xFFFFFFFFu, c.w, off);
                }
                if (lane == 0) red4[s*32 + n*2 + half] = c;
            }
            asm volatile("bar.sync 2, %0;" :: "n"(NCONS) : "memory");

            // finalize: a' = 1 - (1-a)(1-derived)
            if (ITER == 0) {
                if (ctid < NPB) {
                    const int n = n0 + ctid;
                    float4 d0 = red4[s*32 + ctid*2], d1 = red4[s*32 + ctid*2 + 1];
                    unsigned u = tabu[n];
                    float4 an;
                    an.x = 1.f - (1.f - (float)((u      ) & 0xFF)*(1.f/255.f)) * (1.f - (d0.x + d1.x));
                    an.y = 1.f - (1.f - (float)((u >>  8) & 0xFF)*(1.f/255.f)) * (1.f - (d0.y + d1.y));
                    an.z = 1.f - (1.f - (float)((u >> 16) & 0xFF)*(1.f/255.f)) * (1.f - (d0.z + d1.z));
                    an.w = 1.f - (1.f - (float)((u >> 24)       )*(1.f/255.f)) * (1.f - (d0.w + d1.w));
                    g_tabB8[n]  = q8x4(an.x, an.y, an.z, an.w);
                    g_tabA32[n] = an;
                }
            } else {
                if (ctid < 4*NPB) {
                    const int b = ctid >> 4, nl = ctid & 15;
                    const int n = n0 + nl;
                    float dv = redf[s*128 + nl*8 + b] + redf[s*128 + nl*8 + 4 + b];
                    float av = ((const float*)g_tabA32)[n*4 + b];   // exact f32 a1
                    out[b*NN + n] = 1.f - (1.f - av) * (1.f - dv);
                }
            }
        }
    }
}

// ---------------- launcher ----------------------------------------------------
extern "C" void kernel_launch(void* const* d_in, const int* in_sizes, int n_in,
                              void* d_out, int out_size) {
    const float* a0 = (const float*)d_in[0];
    const float* Wm = (const float*)d_in[1];
    const void*  x1 = d_in[2];
    const void*  x2 = d_in[3];
    float* out = (float*)d_out;

    cudaFuncSetAttribute(k_iter<0>, cudaFuncAttributeMaxDynamicSharedMemorySize, SMEM_TOTAL);
    cudaFuncSetAttribute(k_iter<1>, cudaFuncAttributeMaxDynamicSharedMemorySize, SMEM_TOTAL);

    k_iter<0><<<NBLK, NT, SMEM_TOTAL>>>(a0, Wm, x1, x2, out);  // raw X -> packed + u8/f32 a1
    k_iter<1><<<NBLK, NT, SMEM_TOTAL>>>(a0, Wm, x1, x2, out);  // packed -> out
}

// round 15
// speedup vs baseline: 1.2157x; 1.2157x over previous
#include <cuda_runtime.h>
#include <cuda_fp16.h>
#include <cstdint>

#define NN 20000
#define MM 64
#define WL 8
#define NPAIRS (MM*NN*WL)      /* 10,240,000 pairs per X tensor */
#define NPB 16                 /* n's per chunk */
#define NCHUNK (NN/NPB)        /* 1250 */
#define NBLK 148               /* one block per SM */
#define NT 1024                /* 16 producer + 16 consumer warps */
#define NPROD 512
#define NCONS 512
#define NSTG 4

/* ---- stage: F1h [64][17] uint2 (8704 B) + F2f [16][67] float4 (17152 B) ---- */
#define STG_F2    8704
#define STG_BYTES 25856

/* ---- shared memory layout (bytes) — identical to R12 ---- */
#define OFF_STG   (NN*4)                      /* 80000 : u8 table (4 batches/word) */
#define OFF_PIP   (OFF_STG + NSTG*STG_BYTES)  /* 183424 : piP half2[32*64]     */
#define OFF_P12   (OFF_PIP + 8192)            /* 191616 : pi1, pi2             */
#define OFF_RED   (OFF_P12 + 512)             /* 192128 : float4[4][16][2]     */
#define OFF_CTL   (OFF_RED + 2048)            /* 194176 : hdr[4] + 8 mbarriers */
#define SMEM_TOTAL (OFF_CTL + 96)             /* 194272 */

#define FS (1.0f/(255.0f*255.0f))

typedef unsigned long long ull;

// ---------------- device scratch (static) ------------------------------------
__device__ unsigned g_cx1[NPAIRS];   // packed (i0 | i1<<16)
__device__ unsigned g_cx2[NPAIRS];
__device__ unsigned g_tabB8[NN];     // a1 as 4 x u8 (gather table for iter 1)
__device__ float4   g_tabA32[NN];    // a1 exact f32 (finalize sidecar)
__device__ unsigned g_piP[2048];     // half2 pi pairs (published by iter-0 block 0)
__device__ float    g_p12[2*MM];     // pi1, pi2
__device__ int      g_tick[2] = {0, 0};

// ---------------- small helpers ----------------------------------------------
__device__ __forceinline__ unsigned s2u(const void* p) {
    return (unsigned)__cvta_generic_to_shared(p);
}
__device__ __forceinline__ void mbar_init(unsigned a, unsigned cnt) {
    asm volatile("mbarrier.init.shared.b64 [%0], %1;" :: "r"(a), "r"(cnt) : "memory");
}
__device__ __forceinline__ void mbar_arrive(unsigned a) {
    asm volatile("mbarrier.arrive.release.cta.shared::cta.b64 _, [%0];" :: "r"(a) : "memory");
}
__device__ __forceinline__ void mbar_wait(unsigned a, unsigned parity) {
    asm volatile(
        "{\n\t.reg .pred P;\n\t"
        "WL_%=:\n\t"
        "mbarrier.try_wait.parity.acquire.cta.shared::cta.b64 P, [%0], %1, 0x989680;\n\t"
        "@P bra.uni WD_%=;\n\t"
        "bra.uni WL_%=;\n\t"
        "WD_%=:\n\t}"
        :: "r"(a), "r"(parity) : "memory");
}
__device__ __forceinline__ ull pack2(float lo, float hi) {
    ull r; asm("mov.b64 %0, {%1, %2};" : "=l"(r) : "f"(lo), "f"(hi)); return r;
}
__device__ __forceinline__ float2 unpack2(ull v) {
    float2 f; asm("mov.b64 {%0, %1}, %2;" : "=f"(f.x), "=f"(f.y) : "l"(v)); return f;
}
__device__ __forceinline__ void fma2(ull& d, ull a, ull b) {
    asm("fma.rn.f32x2 %0, %1, %2, %0;" : "+l"(d) : "l"(a), "l"(b));
}
// u8x4 word -> exact half2 of bytes {b0,b1} / {b2,b3} (PRMT exponent-offset trick)
__device__ __forceinline__ __half2 h1024() {
    unsigned u = 0x64006400u; return *(__half2*)&u;
}
__device__ __forceinline__ __half2 cvtlo(unsigned A) {
    unsigned r = __byte_perm(A, 0x64646464u, 0x4140);
    return __hsub2(*(__half2*)&r, h1024());
}
__device__ __forceinline__ __half2 cvthi(unsigned A) {
    unsigned r = __byte_perm(A, 0x64646464u, 0x4342);
    return __hsub2(*(__half2*)&r, h1024());
}
// gather: 8 independent products, max tree (raw byte products, >= 0)
__device__ __forceinline__ void gath8(const unsigned* pk, const unsigned* __restrict__ tab,
                                      __half2& ga, __half2& gb) {
    __half2 px[8], py[8];
    #pragma unroll
    for (int w = 0; w < 8; w++) {
        unsigned A = tab[pk[w] & 0xFFFFu];
        unsigned B = tab[pk[w] >> 16];
        px[w] = __hmul2(cvtlo(A), cvtlo(B));
        py[w] = __hmul2(cvthi(A), cvthi(B));
    }
    #pragma unroll
    for (int s = 4; s > 0; s >>= 1)
        #pragma unroll
        for (int w = 0; w < s; w++) {
            px[w] = __hmax2(px[w], px[w + s]);
            py[w] = __hmax2(py[w], py[w + s]);
        }
    ga = px[0]; gb = py[0];
}
__device__ __forceinline__ unsigned q8x4(float a, float b, float c, float d) {
    unsigned r =  __float2uint_rn(__saturatef(a) * 255.f);
    r |= __float2uint_rn(__saturatef(b) * 255.f) << 8;
    r |= __float2uint_rn(__saturatef(c) * 255.f) << 16;
    r |= __float2uint_rn(__saturatef(d) * 255.f) << 24;
    return r;
}

// ---------------- main iteration kernel --------------------------------------
template<int ITER>
__global__ void __launch_bounds__(NT, 1) k_iter(const float* __restrict__ a0,
                                                const float* __restrict__ Wm,
                                                const void* __restrict__ x1,
                                                const void* __restrict__ x2,
                                                float* __restrict__ out) {
    extern __shared__ char smem[];
    unsigned* tabu = (unsigned*)smem;                 // [NN] u8x4
    __half2*  piPh = (__half2*)(smem + OFF_PIP);      // [32*64]
    float*    pi1s = (float*) (smem + OFF_P12);
    float*    pi2s = pi1s + MM;
    float4*   red4 = (float4*)(smem + OFF_RED);       // [4][16][2]
    float*    redf = (float*) (smem + OFF_RED);
    volatile int* hdr = (volatile int*)(smem + OFF_CTL);  // [4]
    const unsigned mb_full  = s2u(smem + OFF_CTL + 16);   // 4 x 8B
    const unsigned mb_empty = s2u(smem + OFF_CTL + 48);   // 4 x 8B

    const int tid  = threadIdx.x;
    const int warp = tid >> 5, lane = tid & 31;

    if (blockIdx.x == 0 && tid == 0) g_tick[ITER ^ 1] = 0;
    if (tid < NSTG) {
        mbar_init(mb_full  + 8*tid, NPROD);
        mbar_init(mb_empty + 8*tid, NCONS);
    }

    int is64 = 0;

    if (ITER == 0) {
        // ===== preamble: u8 4-batch a-table from a0 =====
        for (int i = tid; i < NN; i += NT)
            tabu[i] = q8x4(__ldg(a0 + i), __ldg(a0 + NN + i),
                           __ldg(a0 + 2*NN + i), __ldg(a0 + 3*NN + i));

        // ===== preamble: softmax over 64x64 W -> piPh (half2), pi1, pi2 =====
        {
            float* sp = (float*)(smem + OFF_STG);
            float v4[4];
            float lm = -1e30f;
            #pragma unroll
            for (int t = 0; t < 4; t++) {
                float v = __ldg(Wm + tid + t*NT);
                v4[t] = v;
                lm = fmaxf(lm, v);
            }
            #pragma unroll
            for (int off = 16; off > 0; off >>= 1)
                lm = fmaxf(lm, __shfl_xor_sync(0xFFFFFFFFu, lm, off));
            if (lane == 0) redf[warp] = lm;
            __syncthreads();
            float m = -1e30f;
            #pragma unroll
            for (int w = 0; w < 32; w++) m = fmaxf(m, redf[w]);
            __syncthreads();
            float ls = 0.f;
            #pragma unroll
            for (int t = 0; t < 4; t++) {
                float e = expf(v4[t] - m);
                sp[tid + t*NT] = e;
                ls += e;
            }
            #pragma unroll
            for (int off = 16; off > 0; off >>= 1)
                ls += __shfl_xor_sync(0xFFFFFFFFu, ls, off);
            if (lane == 0) redf[32 + warp] = ls;
            __syncthreads();
            float tot = 0.f;
            #pragma unroll
            for (int w = 0; w < 32; w++) tot += redf[32 + w];
            const float inv = 1.f / tot;

            for (int i = tid; i < 2048; i += NT) {
                int kp = i >> 6, j = i & 63;
                __half2 h = __floats2half2_rn(sp[j*MM + 2*kp] * inv, sp[j*MM + 2*kp + 1] * inv);
                piPh[i] = h;
                if (blockIdx.x == 0) g_piP[i] = *(unsigned*)&h;   // publish for iter 1
            }
            if (tid < MM) {
                float s = 0.f;
                #pragma unroll 16
                for (int k = 0; k < MM; k++) s += sp[tid*MM + k];
                pi1s[tid] = s * inv;
                if (blockIdx.x == 0) g_p12[tid] = s * inv;
            } else if (tid < 2*MM) {
                int k = tid - MM;
                float s = 0.f;
                #pragma unroll 16
                for (int j = 0; j < MM; j++) s += sp[j*MM + k];
                pi2s[k] = s * inv;
                if (blockIdx.x == 0) g_p12[tid] = s * inv;
            }
        }

        // ===== preamble: dtype probe =====
        {
            const unsigned* x1u = (const unsigned*)x1;
            int nz = (x1u[2*tid + 1] != 0u) | (x1u[2*(tid + NT) + 1] != 0u);
            is64 = !__syncthreads_or(nz);
        }
    } else {
        // ===== slim preamble: table from a1 (u8), pi from iter-0 globals =====
        for (int i = tid; i < NN; i += NT) tabu[i] = g_tabB8[i];
        for (int i = tid; i < 2048; i += NT) {
            unsigned v = g_piP[i];
            piPh[i] = *(__half2*)&v;
        }
        if (tid < 2*MM) pi1s[tid] = g_p12[tid];   // pi2s = pi1s + 64
    }
    __syncthreads();   // scratch dead; tab/piP/pi/mbar visible to all

    if (tid < NPROD) {
        // ============ PRODUCER: 2 (j, nl) tasks per thread per chunk ============
        for (int i = 0; ; i++) {
            const int s = i & 3, ks = i >> 2;
            if (i >= NSTG) mbar_wait(mb_empty + 8*s, (ks - 1) & 1);
            if (tid == 0) hdr[s] = atomicAdd(&g_tick[ITER], 1);
            asm volatile("bar.sync 1, %0;" :: "n"(NPROD) : "memory");
            const int chunk = hdr[s];
            if (chunk >= NCHUNK) { mbar_arrive(mb_full + 8*s); break; }
            const int n0 = chunk * NPB;
            uint2*  F1h = (uint2*) (smem + OFF_STG + s*STG_BYTES);
            float4* F2f = (float4*)(smem + OFF_STG + s*STG_BYTES + STG_F2);

            #pragma unroll
            for (int p = 0; p < 2; p++) {
                const int t  = p*NPROD + tid;
                const int j  = t >> 4;
                const int nl = t & 15;
                const size_t pb = ((size_t)j * NN + n0 + nl) * WL;
                unsigned pk1[8], pk2[8];
                if (ITER == 0) {
                    if (is64) {
                        const uint4* c1 = (const uint4*)x1 + pb;
                        const uint4* c2 = (const uint4*)x2 + pb;
                        #pragma unroll
                        for (int w = 0; w < 8; w++) { uint4 v = __ldcs(c1 + w); pk1[w] = v.x | (v.z << 16); }
                        #pragma unroll
                        for (int w = 0; w < 8; w++) { uint4 v = __ldcs(c2 + w); pk2[w] = v.x | (v.z << 16); }
                    } else {
                        const uint4* c1 = (const uint4*)x1 + (pb >> 1);
                        const uint4* c2 = (const uint4*)x2 + (pb >> 1);
                        #pragma unroll
                        for (int w = 0; w < 4; w++) {
                            uint4 v = __ldcs(c1 + w);
                            pk1[2*w] = v.x | (v.y << 16); pk1[2*w+1] = v.z | (v.w << 16);
                        }
                        #pragma unroll
                        for (int w = 0; w < 4; w++) {
                            uint4 v = __ldcs(c2 + w);
                            pk2[2*w] = v.x | (v.y << 16); pk2[2*w+1] = v.z | (v.w << 16);
                        }
                    }
                    ((uint4*)(g_cx1 + pb))[0] = make_uint4(pk1[0], pk1[1], pk1[2], pk1[3]);
                    ((uint4*)(g_cx1 + pb))[1] = make_uint4(pk1[4], pk1[5], pk1[6], pk1[7]);
                    ((uint4*)(g_cx2 + pb))[0] = make_uint4(pk2[0], pk2[1], pk2[2], pk2[3]);
                    ((uint4*)(g_cx2 + pb))[1] = make_uint4(pk2[4], pk2[5], pk2[6], pk2[7]);
                } else {
                    const uint4* c1 = (const uint4*)(g_cx1 + pb);
                    const uint4* c2 = (const uint4*)(g_cx2 + pb);
                    uint4 q0 = __ldg(c1), q1 = __ldg(c1 + 1);
                    uint4 r0 = __ldg(c2), r1 = __ldg(c2 + 1);
                    pk1[0]=q0.x; pk1[1]=q0.y; pk1[2]=q0.z; pk1[3]=q0.w;
                    pk1[4]=q1.x; pk1[5]=q1.y; pk1[6]=q1.z; pk1[7]=q1.w;
                    pk2[0]=r0.x; pk2[1]=r0.y; pk2[2]=r0.z; pk2[3]=r0.w;
                    pk2[4]=r1.x; pk2[5]=r1.y; pk2[6]=r1.z; pk2[7]=r1.w;
                }
                __half2 f1a, f1b, f2a, f2b;
                gath8(pk1, tabu, f1a, f1b);
                gath8(pk2, tabu, f2a, f2b);
                F1h[j*17 + nl] = make_uint2(*(unsigned*)&f1a, *(unsigned*)&f1b);  // raw products
                float2 lo = __half22float2(f2a), hi = __half22float2(f2b);
                F2f[nl*67 + j] = make_float4(lo.x*FS, lo.y*FS, hi.x*FS, hi.y*FS); // true units
            }
            mbar_arrive(mb_full + 8*s);
        }
    } else {
        // ============ CONSUMER: bilinear + reduce + finalize (R12-exact) =========
        const int ctid = tid - NPROD;          // 0..511
        const int jj = ctid & 63;              // pi column
        const int g8 = ctid >> 6;              // 0..7 -> n = g8, g8+8
        const int half = (ctid >> 5) & 1;
        const float p1 = pi1s[jj], p2 = pi2s[jj];
        for (int i = 0; ; i++) {
            const int s = i & 3, ks = i >> 2;
            mbar_wait(mb_full + 8*s, ks & 1);
            const int chunk = hdr[s];
            if (chunk >= NCHUNK) break;
            const int n0 = chunk * NPB;
            const uint2*  F1h = (const uint2*) (smem + OFF_STG + s*STG_BYTES);
            const float4* F2f = (const float4*)(smem + OFF_STG + s*STG_BYTES + STG_F2);

            ull mv00 = 0ull, mv01 = 0ull, mv10 = 0ull, mv11 = 0ull;   // [n][b01/b23]
            const ulonglong2* fbA = (const ulonglong2*)(F2f + g8*67);
            const ulonglong2* fbB = (const ulonglong2*)(F2f + (g8+8)*67);
            #pragma unroll 8
            for (int kp = 0; kp < 32; kp++) {
                float2 pw = __half22float2(piPh[kp*64 + jj]);
                ull pwx = pack2(pw.x, pw.x);
                ull pwy = pack2(pw.y, pw.y);
                ulonglong2 A0 = fbA[2*kp], B0 = fbA[2*kp + 1];
                ulonglong2 A1 = fbB[2*kp], B1 = fbB[2*kp + 1];
                fma2(mv00, pwx, A0.x); fma2(mv01, pwx, A0.y);
                fma2(mv00, pwy, B0.x); fma2(mv01, pwy, B0.y);
                fma2(mv10, pwx, A1.x); fma2(mv11, pwx, A1.y);
                fma2(mv10, pwy, B1.x); fma2(mv11, pwy, B1.y);
            }
            uint2  hpA  = F1h[jj*17 + g8];
            uint2  hpB  = F1h[jj*17 + g8 + 8];
            float4 f2vA = F2f[g8*67 + jj];
            float4 f2vB = F2f[(g8+8)*67 + jj];
            mbar_arrive(mb_empty + 8*s);   // stage reads done -> release early

            #pragma unroll
            for (int r = 0; r < 2; r++) {
                const int n = g8 + r*8;
                float2 ma = unpack2(r ? mv10 : mv00);
                float2 mb = unpack2(r ? mv11 : mv01);
                uint2  hp  = r ? hpB : hpA;
                float4 f2v = r ? f2vB : f2vA;
                float2 f01 = __half22float2(*(__half2*)&hp.x);
                float2 f23 = __half22float2(*(__half2*)&hp.y);
                float4 c;   // c = FS*f1raw*(p1 - mv) + p2*F2true
                c.x = FS*f01.x*(p1 - ma.x) + p2*f2v.x;
                c.y = FS*f01.y*(p1 - ma.y) + p2*f2v.y;
                c.z = FS*f23.x*(p1 - mb.x) + p2*f2v.z;
                c.w = FS*f23.y*(p1 - mb.y) + p2*f2v.w;
                #pragma unroll
                for (int off = 16; off > 0; off >>= 1) {
                    c.x += __shfl_xor_sync(0xFFFFFFFFu, c.x, off);
                    c.y += __shfl_xor_sync(0xFFFFFFFFu, c.y, off);
                    c.z += __shfl_xor_sync(0xFFFFFFFFu, c.z, off);
                    c.w += __shfl_xor_sync(0xFFFFFFFFu, c.w, off);
                }
                if (lane == 0) red4[s*32 + n*2 + half] = c;
            }
            asm volatile("bar.sync 2, %0;" :: "n"(NCONS) : "memory");

            // finalize: a' = 1 - (1-a)(1-derived)
            if (ITER == 0) {
                if (ctid < NPB) {
                    const int n = n0 + ctid;
                    float4 d0 = red4[s*32 + ctid*2], d1 = red4[s*32 + ctid*2 + 1];
                    unsigned u = tabu[n];
                    float4 an;
                    an.x = 1.f - (1.f - (float)((u      ) & 0xFF)*(1.f/255.f)) * (1.f - (d0.x + d1.x));
                    an.y = 1.f - (1.f - (float)((u >>  8) & 0xFF)*(1.f/255.f)) * (1.f - (d0.y + d1.y));
                    an.z = 1.f - (1.f - (float)((u >> 16) & 0xFF)*(1.f/255.f)) * (1.f - (d0.z + d1.z));
                    an.w = 1.f - (1.f - (float)((u >> 24)       )*(1.f/255.f)) * (1.f - (d0.w + d1.w));
                    g_tabB8[n]  = q8x4(an.x, an.y, an.z, an.w);
                    g_tabA32[n] = an;
                }
            } else {
                if (ctid < 4*NPB) {
                    const int b = ctid >> 4, nl = ctid & 15;
                    const int n = n0 + nl;
                    float dv = redf[s*128 + nl*8 + b] + redf[s*128 + nl*8 + 4 + b];
                    float av = ((const float*)g_tabA32)[n*4 + b];   // exact f32 a1
                    out[b*NN + n] = 1.f - (1.f - av) * (1.f - dv);
                }
            }
        }
    }
}

// ---------------- launcher ----------------------------------------------------
extern "C" void kernel_launch(void* const* d_in, const int* in_sizes, int n_in,
                              void* d_out, int out_size) {
    const float* a0 = (const float*)d_in[0];
    const float* Wm = (const float*)d_in[1];
    const void*  x1 = d_in[2];
    const void*  x2 = d_in[3];
    float* out = (float*)d_out;

    cudaFuncSetAttribute(k_iter<0>, cudaFuncAttributeMaxDynamicSharedMemorySize, SMEM_TOTAL);
    cudaFuncSetAttribute(k_iter<1>, cudaFuncAttributeMaxDynamicSharedMemorySize, SMEM_TOTAL);

    k_iter<0><<<NBLK, NT, SMEM_TOTAL>>>(a0, Wm, x1, x2, out);  // raw X -> packed + u8/f32 a1
    k_iter<1><<<NBLK, NT, SMEM_TOTAL>>>(a0, Wm, x1, x2, out);  // packed -> out
}

// round 16
// speedup vs baseline: 1.3887x; 1.1423x over previous
#include <cuda_runtime.h>
#include <cuda_fp16.h>
#include <cstdint>

#define NN 20000
#define MM 64
#define WL 8
#define NPAIRS (MM*NN*WL)      /* 10,240,000 pairs per X tensor */
#define NPB 16                 /* n's per chunk */
#define NCHUNK (NN/NPB)        /* 1250 */
#define NBLK 148               /* one block per SM */
#define NT 1024                /* 16 producer + 16 consumer warps */
#define NPROD 512
#define NCONS 512
#define NSTG 4

/* ---- stage: F1h [64][17] uint2 (8704 B) + F2h [16][70] uint2 (8960 B) ---- */
#define STG_F2    8704
#define STG_BYTES 17664

/* ---- shared memory layout (bytes) ---- */
#define OFF_STG   (NN*4)                      /* 80000 : u8 table (4 batches/word) */
#define OFF_PIP   (OFF_STG + NSTG*STG_BYTES)  /* 150656 : piP half2[32*64]      */
#define OFF_P12   (OFF_PIP + 8192)            /* 158848 : pi1, pi2              */
#define OFF_RED   (OFF_P12 + 512)             /* 159360 : float4[4][16][2]      */
#define OFF_CTL   (OFF_RED + 2048)            /* 161408 : hdr[4] + 8 mbarriers  */
#define SMEM_TOTAL (OFF_CTL + 96)             /* 161504 */

#define FS (1.0f/(255.0f*255.0f))

typedef unsigned long long ull;

// ---------------- device scratch (static) ------------------------------------
__device__ unsigned g_cx1[NPAIRS];   // packed (i0 | i1<<16)
__device__ unsigned g_cx2[NPAIRS];
__device__ unsigned g_tabB8[NN];     // a1 as 4 x u8 (gather table for iter 1)
__device__ float4   g_tabA32[NN];    // a1 exact f32 (finalize sidecar)
__device__ unsigned g_piP[2048];     // half2 pi pairs (published by iter-0 block 0)
__device__ float    g_p12[2*MM];     // pi1, pi2
__device__ int      g_tick[2] = {0, 0};

// ---------------- small helpers ----------------------------------------------
__device__ __forceinline__ unsigned s2u(const void* p) {
    return (unsigned)__cvta_generic_to_shared(p);
}
__device__ __forceinline__ void mbar_init(unsigned a, unsigned cnt) {
    asm volatile("mbarrier.init.shared.b64 [%0], %1;" :: "r"(a), "r"(cnt) : "memory");
}
__device__ __forceinline__ void mbar_arrive(unsigned a) {
    asm volatile("mbarrier.arrive.release.cta.shared::cta.b64 _, [%0];" :: "r"(a) : "memory");
}
__device__ __forceinline__ void mbar_wait(unsigned a, unsigned parity) {
    asm volatile(
        "{\n\t.reg .pred P;\n\t"
        "WL_%=:\n\t"
        "mbarrier.try_wait.parity.acquire.cta.shared::cta.b64 P, [%0], %1, 0x989680;\n\t"
        "@P bra.uni WD_%=;\n\t"
        "bra.uni WL_%=;\n\t"
        "WD_%=:\n\t}"
        :: "r"(a), "r"(parity) : "memory");
}
__device__ __forceinline__ __half2 u2h(unsigned u) { return *(__half2*)&u; }
// u8x4 word -> exact half2 of bytes {b0,b1} / {b2,b3} (PRMT exponent-offset trick)
__device__ __forceinline__ __half2 h1024() {
    unsigned u = 0x64006400u; return *(__half2*)&u;
}
__device__ __forceinline__ __half2 cvtlo(unsigned A) {
    unsigned r = __byte_perm(A, 0x64646464u, 0x4140);
    return __hsub2(*(__half2*)&r, h1024());
}
__device__ __forceinline__ __half2 cvthi(unsigned A) {
    unsigned r = __byte_perm(A, 0x64646464u, 0x4342);
    return __hsub2(*(__half2*)&r, h1024());
}
// gather: 8 independent products, max tree (raw byte products, >= 0)
__device__ __forceinline__ void gath8(const unsigned* pk, const unsigned* __restrict__ tab,
                                      __half2& ga, __half2& gb) {
    __half2 px[8], py[8];
    #pragma unroll
    for (int w = 0; w < 8; w++) {
        unsigned A = tab[pk[w] & 0xFFFFu];
        unsigned B = tab[pk[w] >> 16];
        px[w] = __hmul2(cvtlo(A), cvtlo(B));
        py[w] = __hmul2(cvthi(A), cvthi(B));
    }
    #pragma unroll
    for (int s = 4; s > 0; s >>= 1)
        #pragma unroll
        for (int w = 0; w < s; w++) {
            px[w] = __hmax2(px[w], px[w + s]);
            py[w] = __hmax2(py[w], py[w + s]);
        }
    ga = px[0]; gb = py[0];
}
__device__ __forceinline__ unsigned q8x4(float a, float b, float c, float d) {
    unsigned r =  __float2uint_rn(__saturatef(a) * 255.f);
    r |= __float2uint_rn(__saturatef(b) * 255.f) << 8;
    r |= __float2uint_rn(__saturatef(c) * 255.f) << 16;
    r |= __float2uint_rn(__saturatef(d) * 255.f) << 24;
    return r;
}

// ---------------- main iteration kernel --------------------------------------
template<int ITER>
__global__ void __launch_bounds__(NT, 1) k_iter(const float* __restrict__ a0,
                                                const float* __restrict__ Wm,
                                                const void* __restrict__ x1,
                                                const void* __restrict__ x2,
                                                float* __restrict__ out) {
    extern __shared__ char smem[];
    unsigned* tabu = (unsigned*)smem;                 // [NN] u8x4
    __half2*  piPh = (__half2*)(smem + OFF_PIP);      // [32*64]
    float*    pi1s = (float*) (smem + OFF_P12);
    float*    pi2s = pi1s + MM;
    float4*   red4 = (float4*)(smem + OFF_RED);       // [4][16][2]
    float*    redf = (float*) (smem + OFF_RED);
    volatile int* hdr = (volatile int*)(smem + OFF_CTL);  // [4]
    const unsigned mb_full  = s2u(smem + OFF_CTL + 16);   // 4 x 8B
    const unsigned mb_empty = s2u(smem + OFF_CTL + 48);   // 4 x 8B

    const int tid  = threadIdx.x;
    const int warp = tid >> 5, lane = tid & 31;

    if (blockIdx.x == 0 && tid == 0) g_tick[ITER ^ 1] = 0;
    if (tid < NSTG) {
        mbar_init(mb_full  + 8*tid, NPROD);
        mbar_init(mb_empty + 8*tid, NCONS);
    }

    int is64 = 0;

    if (ITER == 0) {
        // ===== preamble: u8 4-batch a-table from a0 =====
        for (int i = tid; i < NN; i += NT)
            tabu[i] = q8x4(__ldg(a0 + i), __ldg(a0 + NN + i),
                           __ldg(a0 + 2*NN + i), __ldg(a0 + 3*NN + i));

        // ===== preamble: softmax over 64x64 W -> piPh (half2), pi1, pi2 =====
        {
            float* sp = (float*)(smem + OFF_STG);
            float v4[4];
            float lm = -1e30f;
            #pragma unroll
            for (int t = 0; t < 4; t++) {
                float v = __ldg(Wm + tid + t*NT);
                v4[t] = v;
                lm = fmaxf(lm, v);
            }
            #pragma unroll
            for (int off = 16; off > 0; off >>= 1)
                lm = fmaxf(lm, __shfl_xor_sync(0xFFFFFFFFu, lm, off));
            if (lane == 0) redf[warp] = lm;
            __syncthreads();
            float m = -1e30f;
            #pragma unroll
            for (int w = 0; w < 32; w++) m = fmaxf(m, redf[w]);
            __syncthreads();
            float ls = 0.f;
            #pragma unroll
            for (int t = 0; t < 4; t++) {
                float e = expf(v4[t] - m);
                sp[tid + t*NT] = e;
                ls += e;
            }
            #pragma unroll
            for (int off = 16; off > 0; off >>= 1)
                ls += __shfl_xor_sync(0xFFFFFFFFu, ls, off);
            if (lane == 0) redf[32 + warp] = ls;
            __syncthreads();
            float tot = 0.f;
            #pragma unroll
            for (int w = 0; w < 32; w++) tot += redf[32 + w];
            const float inv = 1.f / tot;

            for (int i = tid; i < 2048; i += NT) {
                int kp = i >> 6, j = i & 63;
                __half2 h = __floats2half2_rn(sp[j*MM + 2*kp] * inv, sp[j*MM + 2*kp + 1] * inv);
                piPh[i] = h;
                if (blockIdx.x == 0) g_piP[i] = *(unsigned*)&h;   // publish for iter 1
            }
            if (tid < MM) {
                float s = 0.f;
                #pragma unroll 16
                for (int k = 0; k < MM; k++) s += sp[tid*MM + k];
                pi1s[tid] = s * inv;
                if (blockIdx.x == 0) g_p12[tid] = s * inv;
            } else if (tid < 2*MM) {
                int k = tid - MM;
                float s = 0.f;
                #pragma unroll 16
                for (int j = 0; j < MM; j++) s += sp[j*MM + k];
                pi2s[k] = s * inv;
                if (blockIdx.x == 0) g_p12[tid] = s * inv;
            }
        }

        // ===== preamble: dtype probe =====
        {
            const unsigned* x1u = (const unsigned*)x1;
            int nz = (x1u[2*tid + 1] != 0u) | (x1u[2*(tid + NT) + 1] != 0u);
            is64 = !__syncthreads_or(nz);
        }
    } else {
        // ===== slim preamble: table from a1 (u8), pi from iter-0 globals =====
        for (int i = tid; i < NN; i += NT) tabu[i] = g_tabB8[i];
        for (int i = tid; i < 2048; i += NT) {
            unsigned v = g_piP[i];
            piPh[i] = *(__half2*)&v;
        }
        if (tid < 2*MM) pi1s[tid] = g_p12[tid];   // pi2s = pi1s + 64
    }
    __syncthreads();   // scratch dead; tab/piP/pi/mbar visible to all

    if (tid < NPROD) {
        // ============ PRODUCER: 2 (j, nl) tasks per thread per chunk ============
        for (int i = 0; ; i++) {
            const int s = i & 3, ks = i >> 2;
            if (i >= NSTG) mbar_wait(mb_empty + 8*s, (ks - 1) & 1);
            if (tid == 0) hdr[s] = atomicAdd(&g_tick[ITER], 1);
            asm volatile("bar.sync 1, %0;" :: "n"(NPROD) : "memory");
            const int chunk = hdr[s];
            if (chunk >= NCHUNK) { mbar_arrive(mb_full + 8*s); break; }
            const int n0 = chunk * NPB;
            uint2* F1h = (uint2*)(smem + OFF_STG + s*STG_BYTES);
            uint2* F2h = (uint2*)(smem + OFF_STG + s*STG_BYTES + STG_F2);

            #pragma unroll
            for (int p = 0; p < 2; p++) {
                const int t  = p*NPROD + tid;
                const int j  = t >> 4;
                const int nl = t & 15;
                const size_t pb = ((size_t)j * NN + n0 + nl) * WL;
                unsigned pk1[8], pk2[8];
                if (ITER == 0) {
                    if (is64) {
                        const uint4* c1 = (const uint4*)x1 + pb;
                        const uint4* c2 = (const uint4*)x2 + pb;
                        #pragma unroll
                        for (int w = 0; w < 8; w++) { uint4 v = __ldcs(c1 + w); pk1[w] = v.x | (v.z << 16); }
                        #pragma unroll
                        for (int w = 0; w < 8; w++) { uint4 v = __ldcs(c2 + w); pk2[w] = v.x | (v.z << 16); }
                    } else {
                        const uint4* c1 = (const uint4*)x1 + (pb >> 1);
                        const uint4* c2 = (const uint4*)x2 + (pb >> 1);
                        #pragma unroll
                        for (int w = 0; w < 4; w++) {
                            uint4 v = __ldcs(c1 + w);
                            pk1[2*w] = v.x | (v.y << 16); pk1[2*w+1] = v.z | (v.w << 16);
                        }
                        #pragma unroll
                        for (int w = 0; w < 4; w++) {
                            uint4 v = __ldcs(c2 + w);
                            pk2[2*w] = v.x | (v.y << 16); pk2[2*w+1] = v.z | (v.w << 16);
                        }
                    }
                    ((uint4*)(g_cx1 + pb))[0] = make_uint4(pk1[0], pk1[1], pk1[2], pk1[3]);
                    ((uint4*)(g_cx1 + pb))[1] = make_uint4(pk1[4], pk1[5], pk1[6], pk1[7]);
                    ((uint4*)(g_cx2 + pb))[0] = make_uint4(pk2[0], pk2[1], pk2[2], pk2[3]);
                    ((uint4*)(g_cx2 + pb))[1] = make_uint4(pk2[4], pk2[5], pk2[6], pk2[7]);
                } else {
                    const uint4* c1 = (const uint4*)(g_cx1 + pb);
                    const uint4* c2 = (const uint4*)(g_cx2 + pb);
                    uint4 q0 = __ldg(c1), q1 = __ldg(c1 + 1);
                    uint4 r0 = __ldg(c2), r1 = __ldg(c2 + 1);
                    pk1[0]=q0.x; pk1[1]=q0.y; pk1[2]=q0.z; pk1[3]=q0.w;
                    pk1[4]=q1.x; pk1[5]=q1.y; pk1[6]=q1.z; pk1[7]=q1.w;
                    pk2[0]=r0.x; pk2[1]=r0.y; pk2[2]=r0.z; pk2[3]=r0.w;
                    pk2[4]=r1.x; pk2[5]=r1.y; pk2[6]=r1.z; pk2[7]=r1.w;
                }
                __half2 f1a, f1b, f2a, f2b;
                gath8(pk1, tabu, f1a, f1b);
                gath8(pk2, tabu, f2a, f2b);
                F1h[j*17 + nl] = make_uint2(*(unsigned*)&f1a, *(unsigned*)&f1b);  // raw products
                F2h[nl*70 + j] = make_uint2(*(unsigned*)&f2a, *(unsigned*)&f2b);  // raw products
            }
            mbar_arrive(mb_full + 8*s);
        }
    } else {
        // ============ CONSUMER: half-bilinear + reduce + finalize ================
        const int ctid = tid - NPROD;          // 0..511
        const int jj = ctid & 63;              // pi column
        const int g8 = ctid >> 6;              // 0..7 -> n = g8, g8+8
        const int half = (ctid >> 5) & 1;
        const float p1 = pi1s[jj], p2 = pi2s[jj];
        for (int i = 0; ; i++) {
            const int s = i & 3, ks = i >> 2;
            mbar_wait(mb_full + 8*s, ks & 1);
            const int chunk = hdr[s];
            if (chunk >= NCHUNK) break;
            const int n0 = chunk * NPB;
            const uint2* F1h = (const uint2*)(smem + OFF_STG + s*STG_BYTES);
            const uint2* F2h = (const uint2*)(smem + OFF_STG + s*STG_BYTES + STG_F2);

            // mv accumulators in half2 (raw-product units)
            __half2 mv00 = __float2half2_rn(0.f), mv01 = mv00, mv10 = mv00, mv11 = mv00;
            const uint4* fbA = (const uint4*)(F2h + g8*70);        // 16B bcast per kp
            const uint4* fbB = (const uint4*)(F2h + (g8+8)*70);
            #pragma unroll 8
            for (int kp = 0; kp < 32; kp++) {
                __half2 pw = piPh[kp*64 + jj];
                __half2 pe = __low2half2(pw);      // (pi_even, pi_even)
                __half2 po = __high2half2(pw);     // (pi_odd,  pi_odd)
                uint4 A = fbA[kp], B = fbB[kp];    // k=2kp: .x/.y, k=2kp+1: .z/.w
                mv00 = __hfma2(pe, u2h(A.x), mv00); mv01 = __hfma2(pe, u2h(A.y), mv01);
                mv00 = __hfma2(po, u2h(A.z), mv00); mv01 = __hfma2(po, u2h(A.w), mv01);
                mv10 = __hfma2(pe, u2h(B.x), mv10); mv11 = __hfma2(pe, u2h(B.y), mv11);
                mv10 = __hfma2(po, u2h(B.z), mv10); mv11 = __hfma2(po, u2h(B.w), mv11);
            }
            uint2 hpA  = F1h[jj*17 + g8];
            uint2 hpB  = F1h[jj*17 + g8 + 8];
            uint2 g2A  = F2h[g8*70 + jj];
            uint2 g2B  = F2h[(g8+8)*70 + jj];
            mbar_arrive(mb_empty + 8*s);   // stage reads done -> release early

            #pragma unroll
            for (int r = 0; r < 2; r++) {
                const int n = g8 + r*8;
                float2 mA = __half22float2(r ? mv10 : mv00);   // raw units
                float2 mB = __half22float2(r ? mv11 : mv01);
                uint2 hp = r ? hpB : hpA;
                uint2 g2 = r ? g2B : g2A;
                float2 f01 = __half22float2(u2h(hp.x));
                float2 f23 = __half22float2(u2h(hp.y));
                float2 e01 = __half22float2(u2h(g2.x));
                float2 e23 = __half22float2(u2h(g2.y));
                float4 c;   // c = FS*( f1raw*(p1 - FS*mvraw) + p2*f2raw )
                c.x = FS*(f01.x*(p1 - FS*mA.x) + p2*e01.x);
                c.y = FS*(f01.y*(p1 - FS*mA.y) + p2*e01.y);
                c.z = FS*(f23.x*(p1 - FS*mB.x) + p2*e23.x);
                c.w = FS*(f23.y*(p1 - FS*mB.y) + p2*e23.y);
                #pragma unroll
                for (int off = 16; off > 0; off >>= 1) {
                    c.x += __shfl_xor_sync(0xFFFFFFFFu, c.x, off);
                    c.y += __shfl_xor_sync(0xFFFFFFFFu, c.y, off);
                    c.z += __shfl_xor_sync(0xFFFFFFFFu, c.z, off);
                    c.w += __shfl_xor_sync(0xFFFFFFFFu, c.w, off);
                }
                if (lane == 0) red4[s*32 + n*2 + half] = c;
            }
            asm volatile("bar.sync 2, %0;" :: "n"(NCONS) : "memory");

            // finalize: a' = 1 - (1-a)(1-derived)
            if (ITER == 0) {
                if (ctid < NPB) {
                    const int n = n0 + ctid;
                    float4 d0 = red4[s*32 + ctid*2], d1 = red4[s*32 + ctid*2 + 1];
                    unsigned u = tabu[n];
                    float4 an;
                    an.x = 1.f - (1.f - (float)((u      ) & 0xFF)*(1.f/255.f)) * (1.f - (d0.x + d1.x));
                    an.y = 1.f - (1.f - (float)((u >>  8) & 0xFF)*(1.f/255.f)) * (1.f - (d0.y + d1.y));
                    an.z = 1.f - (1.f - (float)((u >> 16) & 0xFF)*(1.f/255.f)) * (1.f - (d0.z + d1.z));
                    an.w = 1.f - (1.f - (float)((u >> 24)       )*(1.f/255.f)) * (1.f - (d0.w + d1.w));
                    g_tabB8[n]  = q8x4(an.x, an.y, an.z, an.w);
                    g_tabA32[n] = an;
                }
            } else {
                if (ctid < 4*NPB) {
                    const int b = ctid >> 4, nl = ctid & 15;
                    const int n = n0 + nl;
                    float dv = redf[s*128 + nl*8 + b] + redf[s*128 + nl*8 + 4 + b];
                    float av = ((const float*)g_tabA32)[n*4 + b];   // exact f32 a1
                    out[b*NN + n] = 1.f - (1.f - av) * (1.f - dv);
                }
            }
        }
    }
}

// ---------------- launcher ----------------------------------------------------
extern "C" void kernel_launch(void* const* d_in, const int* in_sizes, int n_in,
                              void* d_out, int out_size) {
    const float* a0 = (const float*)d_in[0];
    const float* Wm = (const float*)d_in[1];
    const void*  x1 = d_in[2];
    const void*  x2 = d_in[3];
    float* out = (float*)d_out;

    cudaFuncSetAttribute(k_iter<0>, cudaFuncAttributeMaxDynamicSharedMemorySize, SMEM_TOTAL);
    cudaFuncSetAttribute(k_iter<1>, cudaFuncAttributeMaxDynamicSharedMemorySize, SMEM_TOTAL);

    k_iter<0><<<NBLK, NT, SMEM_TOTAL>>>(a0, Wm, x1, x2, out);  // raw X -> packed + u8/f32 a1
    k_iter<1><<<NBLK, NT, SMEM_TOTAL>>>(a0, Wm, x1, x2, out);  // packed -> out
}